// round 16
// baseline (speedup 1.0000x reference)
#include <cuda_runtime.h>
#include <cuda_fp16.h>

#define N_NODES 100000
#define N_EDGES 1600000
#define N_GRAPH 1024
#define EMB 32
#define DC 128
#define WPB 8       // warps per block
#define NPW 8       // nodes per warp (register blocking in dense kernels)
#define NTPB 256

// ---------------- scratch (static device globals; no allocation) ----------------
__device__ int    g_deg[N_NODES];        // zeroed by k_pool of previous run (init: BSS zero)
__device__ int    g_rowptr[N_NODES + 1];
__device__ int    g_cursor[N_NODES];
__device__ int2   g_sd[N_EDGES];         // {src, dst} per CSR slot
__device__ int    g_bsums[256];
__device__ int    g_gdeg[N_GRAPH];       // zeroed by k_pool of previous run
__device__ int    g_gptr[N_GRAPH + 1];
__device__ __half g_xwh[(size_t)N_NODES * DC];   // fp16 message payload
__device__ __half g_h1h[(size_t)N_NODES * DC];   // fp16 h (layer-1 for node2, layer-2 for gate/pool)
__device__ float  g_als[N_NODES * 2];
__device__ float  g_ald[N_NODES * 2];
__device__ uint4  g_pk[N_EDGES];         // packed {src, exp0_bits, exp1_bits, 0}
__device__ float  g_gate[N_NODES];

__device__ __forceinline__ float lrelu(float x, float s) { return x > 0.f ? x : s * x; }

// f32x2 packed helpers (sm_103a; ptxas never emits FFMA2 from C++)
__device__ __forceinline__ unsigned long long pack2(float v) {
    unsigned long long r; asm("mov.b64 %0,{%1,%1};" : "=l"(r) : "f"(v)); return r;
}
__device__ __forceinline__ void fma2(unsigned long long& a, unsigned long long x, unsigned long long p) {
    asm("fma.rn.f32x2 %0,%1,%2,%0;" : "+l"(a) : "l"(x), "l"(p));
}
__device__ __forceinline__ float2 unpack2(unsigned long long v) {
    float2 r; asm("mov.b64 {%0,%1},%2;" : "=f"(r.x), "=f"(r.y) : "l"(v)); return r;
}

// store 4 fp32 as 4 fp16 in one 8B write
__device__ __forceinline__ void store_h4(__half* row, int lane, float a, float b, float c, float d) {
    union { uint2 u; __half2 h[2]; } cv;
    cv.h[0] = __float22half2_rn(make_float2(a, b));
    cv.h[1] = __float22half2_rn(make_float2(c, d));
    ((uint2*)row)[lane] = cv.u;
}

// 8 halfs (uint4) * p accumulated into 8 fp32
__device__ __forceinline__ void h8_fma(float* acc, uint4 v, float p) {
    union { unsigned u; __half2 h; } c;
    float2 f;
    c.u = v.x; f = __half22float2(c.h); acc[0] += f.x * p; acc[1] += f.y * p;
    c.u = v.y; f = __half22float2(c.h); acc[2] += f.x * p; acc[3] += f.y * p;
    c.u = v.z; f = __half22float2(c.h); acc[4] += f.x * p; acc[5] += f.y * p;
    c.u = v.w; f = __half22float2(c.h); acc[6] += f.x * p; acc[7] += f.y * p;
}

__device__ __forceinline__ unsigned s2u(const void* p) {
    unsigned a;
    asm("{.reg .u64 t; cvta.to.shared.u64 t,%1; cvt.u32.u64 %0,t;}" : "=r"(a) : "l"(p));
    return a;
}

#define LDSM4(r0, r1, r2, r3, addr) \
    asm volatile("ldmatrix.sync.aligned.m8n8.x4.shared.b16 {%0,%1,%2,%3},[%4];" \
                 : "=r"(r0), "=r"(r1), "=r"(r2), "=r"(r3) : "r"(addr))
#define LDSM4T(r0, r1, r2, r3, addr) \
    asm volatile("ldmatrix.sync.aligned.m8n8.x4.trans.shared.b16 {%0,%1,%2,%3},[%4];" \
                 : "=r"(r0), "=r"(r1), "=r"(r2), "=r"(r3) : "r"(addr))
#define MMA16816(C, a0, a1, a2, a3, b0, b1) \
    asm volatile("mma.sync.aligned.m16n8k16.row.col.f32.f16.f16.f32 " \
                 "{%0,%1,%2,%3},{%4,%5,%6,%7},{%8,%9},{%0,%1,%2,%3};" \
                 : "+f"((C)[0]), "+f"((C)[1]), "+f"((C)[2]), "+f"((C)[3]) \
                 : "r"(a0), "r"(a1), "r"(a2), "r"(a3), "r"(b0), "r"(b1))

// ---------------- CSR build ----------------
// 4 edges per thread: one int4 load, 4 independent atomic chains
__global__ void k_hist(const int* __restrict__ ei, const int* __restrict__ batch) {
    int i = blockIdx.x * blockDim.x + threadIdx.x;
    int e4 = i * 4;
    if (e4 + 3 < N_EDGES) {            // N_EDGES % 4 == 0, covers all edges
        int4 d = *(const int4*)(ei + N_EDGES + e4);
        atomicAdd(&g_deg[d.x], 1);
        atomicAdd(&g_deg[d.y], 1);
        atomicAdd(&g_deg[d.z], 1);
        atomicAdd(&g_deg[d.w], 1);
    }
    if (i < N_NODES) atomicAdd(&g_gdeg[batch[i]], 1);
}

__global__ void k_scan_block() {
    __shared__ int sh[1024];
    int t = threadIdx.x;
    int i = blockIdx.x * 1024 + t;
    int v = (i < N_NODES) ? g_deg[i] : 0;
    sh[t] = v;
    __syncthreads();
    for (int off = 1; off < 1024; off <<= 1) {
        int a = (t >= off) ? sh[t - off] : 0;
        __syncthreads();
        sh[t] += a;
        __syncthreads();
    }
    if (i < N_NODES) g_rowptr[i] = sh[t] - v;
    if (t == 1023) g_bsums[blockIdx.x] = sh[1023];
}

// fused: block-sum scan + add + cursor init + total; last block also builds g_gptr
__global__ void k_scan_add2(int nb) {
    __shared__ int sb[128];
    int t = threadIdx.x;
    if (t < 128) sb[t] = (t < nb) ? g_bsums[t] : 0;
    __syncthreads();
    for (int off = 1; off < 128; off <<= 1) {
        int a = (t < 128 && t >= off) ? sb[t - off] : 0;
        __syncthreads();
        if (t < 128) sb[t] += a;
        __syncthreads();
    }
    int i = blockIdx.x * blockDim.x + t;
    if (i < N_NODES) {
        int b = i >> 10;
        int vv = g_rowptr[i] + (b ? sb[b - 1] : 0);
        g_rowptr[i] = vv;
        g_cursor[i] = vv;
    }
    if (i == 0) g_rowptr[N_NODES] = sb[nb - 1];

    if (blockIdx.x == gridDim.x - 1) {    // graph-pointer scan (1024 entries, 4/thread)
        __shared__ int gs[256];
        int b4 = t * 4;
        int a0 = g_gdeg[b4], a1 = g_gdeg[b4 + 1], a2 = g_gdeg[b4 + 2], a3 = g_gdeg[b4 + 3];
        int tot = a0 + a1 + a2 + a3;
        gs[t] = tot;
        __syncthreads();
        for (int off = 1; off < 256; off <<= 1) {
            int a = (t >= off) ? gs[t - off] : 0;
            __syncthreads();
            gs[t] += a;
            __syncthreads();
        }
        int excl = gs[t] - tot;
        g_gptr[b4]     = excl;
        g_gptr[b4 + 1] = excl + a0;
        g_gptr[b4 + 2] = excl + a0 + a1;
        g_gptr[b4 + 3] = excl + a0 + a1 + a2;
        if (t == 255) g_gptr[N_GRAPH] = gs[255];
    }
}

// 4 edges per thread: int4 loads of src+dst quads, 4 independent atomic->store chains
__global__ void k_scatter(const int* __restrict__ ei) {
    int e4 = (blockIdx.x * blockDim.x + threadIdx.x) * 4;
    if (e4 + 3 >= N_EDGES) return;     // N_EDGES % 4 == 0
    int4 s = *(const int4*)(ei + e4);
    int4 d = *(const int4*)(ei + N_EDGES + e4);
    int p0 = atomicAdd(&g_cursor[d.x], 1);
    int p1 = atomicAdd(&g_cursor[d.y], 1);
    int p2 = atomicAdd(&g_cursor[d.z], 1);
    int p3 = atomicAdd(&g_cursor[d.w], 1);
    g_sd[p0] = make_int2(s.x, d.x);
    g_sd[p1] = make_int2(s.y, d.y);
    g_sd[p2] = make_int2(s.z, d.z);
    g_sd[p3] = make_int2(s.w, d.w);
}

// warp-per-node sort of src keys (dst is row-constant, stays in place)
__global__ void k_rowsortw() {
    __shared__ int buf[WPB][160];
    int wl = threadIdx.x >> 5, lane = threadIdx.x & 31;
    int n = blockIdx.x * WPB + wl;
    if (n >= N_NODES) return;
    int rs = g_rowptr[n], L = g_rowptr[n + 1] - rs;
    if (L <= 1) return;
    if (L <= 32) {
        int v = (lane < L) ? g_sd[rs + lane].x : 0x7fffffff;
#pragma unroll
        for (int k = 2; k <= 32; k <<= 1) {
#pragma unroll
            for (int j = k >> 1; j; j >>= 1) {
                int o = __shfl_xor_sync(~0u, v, j);
                bool up = ((lane & k) == 0);
                bool lo = ((lane & j) == 0);
                v = (up == lo) ? min(v, o) : max(v, o);
            }
        }
        if (lane < L) g_sd[rs + lane].x = v;
    } else if (L <= 64) {
        int i0 = lane, i1 = lane + 32;
        int v0 = (i0 < L) ? g_sd[rs + i0].x : 0x7fffffff;
        int v1 = (i1 < L) ? g_sd[rs + i1].x : 0x7fffffff;
#pragma unroll
        for (int k = 2; k <= 64; k <<= 1) {
#pragma unroll
            for (int j = k >> 1; j; j >>= 1) {
                if (j >= 32) {
                    int lo = min(v0, v1), hi = max(v0, v1);
                    v0 = lo; v1 = hi;
                } else {
                    int o0 = __shfl_xor_sync(~0u, v0, j);
                    int o1 = __shfl_xor_sync(~0u, v1, j);
                    bool up0 = ((i0 & k) == 0), up1 = ((i1 & k) == 0);
                    bool lo0 = ((i0 & j) == 0), lo1 = ((i1 & j) == 0);
                    v0 = (up0 == lo0) ? min(v0, o0) : max(v0, o0);
                    v1 = (up1 == lo1) ? min(v1, o1) : max(v1, o1);
                }
            }
        }
        if (i0 < L) g_sd[rs + i0].x = v0;
        if (i1 < L) g_sd[rs + i1].x = v1;
    } else if (L <= 160) {
        for (int i = lane; i < L; i += 32) buf[wl][i] = g_sd[rs + i].x;
        __syncwarp();
        for (int p = 0; p < L; p++) {
            for (int i = (p & 1) + 2 * lane; i + 1 < L; i += 64) {
                int a = buf[wl][i], b = buf[wl][i + 1];
                if (a > b) { buf[wl][i] = b; buf[wl][i + 1] = a; }
            }
            __syncwarp();
        }
        for (int i = lane; i < L; i += 32) g_sd[rs + i].x = buf[wl][i];
    } else if (lane == 0) {
        int re = rs + L;
        for (int i = rs + 1; i < re; i++) {
            int key = g_sd[i].x;
            int j = i - 1;
            while (j >= rs && g_sd[j].x > key) { g_sd[j + 1].x = g_sd[j].x; j--; }
            g_sd[j + 1].x = key;
        }
    }
}

// ---------------- layer 1: embed + LN + W1 + logits (8 nodes/warp, f32x2) ----------------
__global__ void k_node1(const int* __restrict__ x, const float* __restrict__ emb,
                        const float* __restrict__ lng, const float* __restrict__ lnb,
                        const float* __restrict__ W1, const float* __restrict__ asr,
                        const float* __restrict__ adt) {
    __shared__ ulonglong2 sW[EMB * 32];
    __shared__ float sxn[WPB][NPW][EMB];
    int tid = threadIdx.x;
    int wl = tid >> 5, lane = tid & 31;
    {
        const ulonglong2* W4 = (const ulonglong2*)W1;
        for (int i = tid; i < EMB * 32; i += NTPB) sW[i] = W4[i];
    }
    int nbase = (blockIdx.x * WPB + wl) * NPW;

#pragma unroll
    for (int j = 0; j < NPW; j++) {
        int n = nbase + j;
        float xn = 0.f;
        if (n < N_NODES) {
            int vi = x[n];
            float xv = emb[vi * EMB + lane];
            float m = xv;
            for (int o = 16; o; o >>= 1) m += __shfl_xor_sync(~0u, m, o);
            m *= (1.f / EMB);
            float dv = xv - m;
            float var = dv * dv;
            for (int o = 16; o; o >>= 1) var += __shfl_xor_sync(~0u, var, o);
            var *= (1.f / EMB);
            xn = dv * rsqrtf(var + 1e-5f) * lng[lane] + lnb[lane];
        }
        sxn[wl][j][lane] = xn;
    }
    __syncthreads();

    unsigned long long accA[NPW], accB[NPW];
#pragma unroll
    for (int j = 0; j < NPW; j++) { accA[j] = 0ull; accB[j] = 0ull; }
#pragma unroll
    for (int k = 0; k < EMB; k += 4) {
        ulonglong2 w0 = sW[(k + 0) * 32 + lane];
        ulonglong2 w1 = sW[(k + 1) * 32 + lane];
        ulonglong2 w2 = sW[(k + 2) * 32 + lane];
        ulonglong2 w3 = sW[(k + 3) * 32 + lane];
#pragma unroll
        for (int j = 0; j < NPW; j++) {
            float4 h4 = *(const float4*)&sxn[wl][j][k];
            unsigned long long p;
            p = pack2(h4.x); fma2(accA[j], w0.x, p); fma2(accB[j], w0.y, p);
            p = pack2(h4.y); fma2(accA[j], w1.x, p); fma2(accB[j], w1.y, p);
            p = pack2(h4.z); fma2(accA[j], w2.x, p); fma2(accB[j], w2.y, p);
            p = pack2(h4.w); fma2(accA[j], w3.x, p); fma2(accB[j], w3.y, p);
        }
    }

    float4 as4 = __ldg((const float4*)asr + lane);
    float4 ad4 = __ldg((const float4*)adt + lane);
#pragma unroll
    for (int j = 0; j < NPW; j++) {
        int n = nbase + j;
        float2 lo = unpack2(accA[j]), hi = unpack2(accB[j]);
        float ps = lo.x * as4.x + lo.y * as4.y + hi.x * as4.z + hi.y * as4.w;
        float pd = lo.x * ad4.x + lo.y * ad4.y + hi.x * ad4.z + hi.y * ad4.w;
        for (int o = 8; o; o >>= 1) {
            ps += __shfl_xor_sync(~0u, ps, o);
            pd += __shfl_xor_sync(~0u, pd, o);
        }
        if (n < N_NODES) {
            store_h4(g_xwh + (size_t)n * DC, lane, lo.x, lo.y, hi.x, hi.y);
            if ((lane & 15) == 0) {
                int h = lane >> 4;
                g_als[n * 2 + h] = ps;
                g_ald[n * 2 + h] = pd;
            }
        }
    }
}

// ---------------- edge-parallel: packed {src, exp0, exp1} precompute (2 edges/thread) ----------------
__global__ void k_elog() {
    int p = (blockIdx.x * blockDim.x + threadIdx.x) * 2;
    if (p + 1 >= N_EDGES) return;      // N_EDGES % 2 == 0
    int4 sd2 = *(const int4*)(g_sd + p);   // two {src,dst} records
    float2 a0 = __ldg((const float2*)g_als + sd2.x);
    float2 b0 = __ldg((const float2*)g_ald + sd2.y);
    float2 a1 = __ldg((const float2*)g_als + sd2.z);
    float2 b1 = __ldg((const float2*)g_ald + sd2.w);
    uint4 r0, r1;
    r0.x = (unsigned)sd2.x;
    r0.y = __float_as_uint(__expf(lrelu(a0.x + b0.x, 0.2f)));
    r0.z = __float_as_uint(__expf(lrelu(a0.y + b0.y, 0.2f)));
    r0.w = 0;
    r1.x = (unsigned)sd2.z;
    r1.y = __float_as_uint(__expf(lrelu(a1.x + b1.x, 0.2f)));
    r1.z = __float_as_uint(__expf(lrelu(a1.y + b1.y, 0.2f)));
    r1.w = 0;
    g_pk[p] = r0;
    g_pk[p + 1] = r1;
}

// ---------------- GAT aggregation: warp/node, register-staged packed records ----------------
__global__ void k_agg(const float* __restrict__ bias, float* __restrict__ out2, int layer) {
    int n = blockIdx.x * WPB + (threadIdx.x >> 5);
    int lane = threadIdx.x & 31;
    if (n >= N_NODES) return;

    int rs = g_rowptr[n], re = g_rowptr[n + 1];
    int L = re - rs;
    float2 a = *(const float2*)&g_als[2 * n];
    float2 b = *(const float2*)&g_ald[2 * n];
    float ps0 = __expf(lrelu(a.x + b.x, 0.2f));
    float ps1 = __expf(lrelu(a.y + b.y, 0.2f));

    int half  = lane >> 4;
    int s16   = lane & 15;
    int headb = s16 >> 3;

    float acc[8];
    {
        float pself = (half == 0) ? (headb ? ps1 : ps0) : 0.f;
        uint4 xs = __ldg((const uint4*)(g_xwh + (size_t)n * DC) + s16);
#pragma unroll
        for (int i = 0; i < 8; i++) acc[i] = 0.f;
        h8_fma(acc, xs, pself);
    }

    float s0, s1;
    if (L <= 32) {
        // stage entire row in registers: lane k owns edge rs+k (one LDG.128)
        uint4 rec_l = (lane < L) ? __ldg(g_pk + rs + lane) : make_uint4(0, 0, 0, 0);
        s0 = __uint_as_float(rec_l.y); s1 = __uint_as_float(rec_l.z);
#pragma unroll
        for (int o = 16; o; o >>= 1) {
            s0 += __shfl_xor_sync(~0u, s0, o);
            s1 += __shfl_xor_sync(~0u, s1, o);
        }
#pragma unroll 8
        for (int j = 0; j < L; j += 2) {
            int jj = (j + half) & 31;
            int srcj = __shfl_sync(~0u, (int)rec_l.x, jj);
            float px = __shfl_sync(~0u, __uint_as_float(rec_l.y), jj);
            float py = __shfl_sync(~0u, __uint_as_float(rec_l.z), jj);
            float p = (j + half < L) ? (headb ? py : px) : 0.f;
            uint4 xv = __ldg((const uint4*)(g_xwh + (size_t)srcj * DC) + s16);
            h8_fma(acc, xv, p);
        }
    } else {
        s0 = 0.f; s1 = 0.f;
        for (int k = rs + lane; k < re; k += 32) {
            uint4 rec = __ldg(g_pk + k);
            s0 += __uint_as_float(rec.y);
            s1 += __uint_as_float(rec.z);
        }
#pragma unroll
        for (int o = 16; o; o >>= 1) {
            s0 += __shfl_xor_sync(~0u, s0, o);
            s1 += __shfl_xor_sync(~0u, s1, o);
        }
#pragma unroll 8
        for (int k = rs; k < re; k += 2) {
            int kk = k + half;
            int kc = kk < re ? kk : re - 1;
            uint4 rec = __ldg(g_pk + kc);          // one broadcast LDG.128 per edge
            int src = (int)rec.x;
            float p = (kk < re) ? __uint_as_float(headb ? rec.z : rec.y) : 0.f;
            uint4 xv = __ldg((const uint4*)(g_xwh + (size_t)src * DC) + s16);
            h8_fma(acc, xv, p);
        }
    }

#pragma unroll
    for (int i = 0; i < 8; i++) acc[i] += __shfl_xor_sync(~0u, acc[i], 16);

    float inv0 = 1.f / (s0 + ps0);
    float inv1 = 1.f / (s1 + ps1);
    float invh = headb ? inv1 : inv0;
    int idx = s16 * 2 + half;
    float4 bi = __ldg((const float4*)bias + idx);
    const float* ap = acc + half * 4;
    float4 o;
    o.x = ap[0] * invh + bi.x;
    o.y = ap[1] * invh + bi.y;
    o.z = ap[2] * invh + bi.z;
    o.w = ap[3] * invh + bi.w;
    if (layer == 1) {
        o.x = lrelu(o.x, 0.05f); o.y = lrelu(o.y, 0.05f);
        o.z = lrelu(o.z, 0.05f); o.w = lrelu(o.w, 0.05f);
        store_h4(g_h1h + (size_t)n * DC, idx, o.x, o.y, o.z, o.w);   // fp16 for MMA node2
    } else {
        ((float4*)out2)[(size_t)n * 32 + idx] = o;                   // fp32 h output
        store_h4(g_h1h + (size_t)n * DC, idx, o.x, o.y, o.z, o.w);   // fp16 for gate + pool
    }
}

// ---------------- layer 2 node transform via HMMA: h1h @ W2 + logits ----------------
#define PITCH_H 136   // halfs per smem row (128 + 8 pad)
__global__ void k_node2m(const float* __restrict__ W2, const float* __restrict__ asr,
                         const float* __restrict__ adt) {
    extern __shared__ char dsm[];
    __half* sA = (__half*)dsm;                                 // 128 x PITCH_H
    __half* sB = (__half*)(dsm + 128 * PITCH_H * 2);           // 128 x PITCH_H
    float*  sAs = (float*)(dsm + 2 * 128 * PITCH_H * 2);       // 128
    float*  sAd = sAs + 128;

    int tid = threadIdx.x;
    int wl = tid >> 5, lane = tid & 31;
    int bb = blockIdx.x * 128;

    if (tid < 128) { sAs[tid] = asr[tid]; sAd[tid] = adt[tid]; }
    for (int i = tid; i < 128 * 64; i += NTPB) {
        int k = i >> 6, c2 = i & 63;
        float2 w = *(const float2*)(W2 + k * 128 + c2 * 2);
        *(__half2*)(sB + k * PITCH_H + c2 * 2) = __float22half2_rn(w);
    }
    for (int i = tid; i < 128 * 16; i += NTPB) {
        int r = i >> 4, c = i & 15;
        int rg = bb + r; if (rg >= N_NODES) rg = N_NODES - 1;
        uint4 v = *(const uint4*)(g_h1h + (size_t)rg * DC + c * 8);
        *(uint4*)(sA + r * PITCH_H + c * 8) = v;
    }
    __syncthreads();

    float C[16][4];
#pragma unroll
    for (int t = 0; t < 16; t++) { C[t][0] = 0.f; C[t][1] = 0.f; C[t][2] = 0.f; C[t][3] = 0.f; }

    int g = lane >> 3;
    int rrow = (lane & 7) + ((g & 1) << 3);
    unsigned aBase = s2u(sA + wl * 16 * PITCH_H) + rrow * (PITCH_H * 2) + ((g >> 1) << 4);
    unsigned bBase = s2u(sB) + rrow * (PITCH_H * 2) + ((g >> 1) << 4);

#pragma unroll
    for (int kg = 0; kg < 8; kg++) {
        unsigned a0, a1, a2, a3;
        LDSM4(a0, a1, a2, a3, aBase + kg * 32);
#pragma unroll
        for (int nt = 0; nt < 8; nt++) {
            unsigned b0, b1, b2, b3;
            LDSM4T(b0, b1, b2, b3, bBase + kg * 16 * (PITCH_H * 2) + nt * 32);
            MMA16816(C[nt * 2],     a0, a1, a2, a3, b0, b1);
            MMA16816(C[nt * 2 + 1], a0, a1, a2, a3, b2, b3);
        }
    }

    int q = lane & 3;
    int r0 = wl * 16 + (lane >> 2);
    int n0 = bb + r0, n1 = n0 + 8;
    float psA0 = 0.f, psB0 = 0.f, pdA0 = 0.f, pdB0 = 0.f;
    float psA1 = 0.f, psB1 = 0.f, pdA1 = 0.f, pdB1 = 0.f;
#pragma unroll
    for (int nt = 0; nt < 16; nt++) {
        int col = nt * 8 + q * 2;
        float c0 = C[nt][0], c1 = C[nt][1], c2 = C[nt][2], c3 = C[nt][3];
        if (n0 < N_NODES)
            *(__half2*)(g_xwh + (size_t)n0 * DC + col) = __floats2half2_rn(c0, c1);
        if (n1 < N_NODES)
            *(__half2*)(g_xwh + (size_t)n1 * DC + col) = __floats2half2_rn(c2, c3);
        float as0 = sAs[col], as1 = sAs[col + 1];
        float ad0 = sAd[col], ad1 = sAd[col + 1];
        float s_r0 = c0 * as0 + c1 * as1, d_r0 = c0 * ad0 + c1 * ad1;
        float s_r1 = c2 * as0 + c3 * as1, d_r1 = c2 * ad0 + c3 * ad1;
        if (nt < 8) { psA0 += s_r0; pdA0 += d_r0; psA1 += s_r1; pdA1 += d_r1; }
        else        { psB0 += s_r0; pdB0 += d_r0; psB1 += s_r1; pdB1 += d_r1; }
    }
#pragma unroll
    for (int o = 1; o <= 2; o <<= 1) {
        psA0 += __shfl_xor_sync(~0u, psA0, o); psB0 += __shfl_xor_sync(~0u, psB0, o);
        pdA0 += __shfl_xor_sync(~0u, pdA0, o); pdB0 += __shfl_xor_sync(~0u, pdB0, o);
        psA1 += __shfl_xor_sync(~0u, psA1, o); psB1 += __shfl_xor_sync(~0u, psB1, o);
        pdA1 += __shfl_xor_sync(~0u, pdA1, o); pdB1 += __shfl_xor_sync(~0u, pdB1, o);
    }
    if (q == 0) {
        if (n0 < N_NODES) {
            g_als[2 * n0] = psA0; g_als[2 * n0 + 1] = psB0;
            g_ald[2 * n0] = pdA0; g_ald[2 * n0 + 1] = pdB0;
        }
        if (n1 < N_NODES) {
            g_als[2 * n1] = psA1; g_als[2 * n1 + 1] = psB1;
            g_ald[2 * n1] = pdA1; g_ald[2 * n1 + 1] = pdB1;
        }
    }
}

// ---------------- gate MLP via HMMA: h(fp16) @ gw1 -> lrelu -> @ gw2 ----------------
#define PB_G 72   // halfs per smem row for gw1 tile (64 + 8 pad)
__global__ void k_gatem(const float* __restrict__ gw1, const float* __restrict__ gb1,
                        const float* __restrict__ gw2, const float* __restrict__ gb2) {
    extern __shared__ char dsm[];
    __half* sA = (__half*)dsm;                                 // 128 x PITCH_H (h rows)
    __half* sB = (__half*)(dsm + 128 * PITCH_H * 2);           // 128 x PB_G (gw1)
    float*  sGb = (float*)(dsm + 128 * PITCH_H * 2 + 128 * PB_G * 2);  // 64
    float*  sGw = sGb + 64;                                    // 64

    int tid = threadIdx.x;
    int wl = tid >> 5, lane = tid & 31;
    int bb = blockIdx.x * 128;

    if (tid < 64) { sGb[tid] = gb1[tid]; sGw[tid] = gw2[tid]; }
    for (int i = tid; i < 128 * 32; i += NTPB) {
        int k = i >> 5, c2 = i & 31;
        float2 w = *(const float2*)(gw1 + k * 64 + c2 * 2);
        *(__half2*)(sB + k * PB_G + c2 * 2) = __float22half2_rn(w);
    }
    for (int i = tid; i < 128 * 16; i += NTPB) {
        int r = i >> 4, c = i & 15;
        int rg = bb + r; if (rg >= N_NODES) rg = N_NODES - 1;
        uint4 v = *(const uint4*)(g_h1h + (size_t)rg * DC + c * 8);
        *(uint4*)(sA + r * PITCH_H + c * 8) = v;
    }
    __syncthreads();

    float C[8][4];
#pragma unroll
    for (int t = 0; t < 8; t++) { C[t][0] = 0.f; C[t][1] = 0.f; C[t][2] = 0.f; C[t][3] = 0.f; }

    int g = lane >> 3;
    int rrow = (lane & 7) + ((g & 1) << 3);
    unsigned aBase = s2u(sA + wl * 16 * PITCH_H) + rrow * (PITCH_H * 2) + ((g >> 1) << 4);
    unsigned bBase = s2u(sB) + rrow * (PB_G * 2) + ((g >> 1) << 4);

#pragma unroll
    for (int kg = 0; kg < 8; kg++) {
        unsigned a0, a1, a2, a3;
        LDSM4(a0, a1, a2, a3, aBase + kg * 32);
#pragma unroll
        for (int nt = 0; nt < 4; nt++) {
            unsigned b0, b1, b2, b3;
            LDSM4T(b0, b1, b2, b3, bBase + kg * 16 * (PB_G * 2) + nt * 32);
            MMA16816(C[nt * 2],     a0, a1, a2, a3, b0, b1);
            MMA16816(C[nt * 2 + 1], a0, a1, a2, a3, b2, b3);
        }
    }

    int q = lane & 3;
    int r0 = wl * 16 + (lane >> 2);
    int n0 = bb + r0, n1 = n0 + 8;
    float g0 = 0.f, g1 = 0.f;
#pragma unroll
    for (int nt = 0; nt < 8; nt++) {
        int col = nt * 8 + q * 2;
        float b0 = sGb[col], b1 = sGb[col + 1];
        float w0 = sGw[col], w1 = sGw[col + 1];
        g0 += lrelu(C[nt][0] + b0, 0.05f) * w0 + lrelu(C[nt][1] + b1, 0.05f) * w1;
        g1 += lrelu(C[nt][2] + b0, 0.05f) * w0 + lrelu(C[nt][3] + b1, 0.05f) * w1;
    }
#pragma unroll
    for (int o = 1; o <= 2; o <<= 1) {
        g0 += __shfl_xor_sync(~0u, g0, o);
        g1 += __shfl_xor_sync(~0u, g1, o);
    }
    if (q == 0) {
        float gbias = *gb2;
        if (n0 < N_NODES) g_gate[n0] = g0 + gbias;
        if (n1 < N_NODES) g_gate[n1] = g1 + gbias;
    }
}

// ---------------- per-graph softmax pooling (fp16 h) + scratch re-zero ----------------
__global__ void k_pool(float* __restrict__ zout) {
    int g = blockIdx.x;
    int t = threadIdx.x;
    int s = g_gptr[g], e = g_gptr[g + 1];
    __shared__ float red[128];
    __shared__ float wbuf[128];

    float lm = -3.4e38f;
    for (int i = s + t; i < e; i += 128) lm = fmaxf(lm, g_gate[i]);
    red[t] = lm;
    __syncthreads();
    for (int o = 64; o; o >>= 1) { if (t < o) red[t] = fmaxf(red[t], red[t + o]); __syncthreads(); }
    float gm = red[0];
    __syncthreads();

    float ls = 0.f;
    for (int i = s + t; i < e; i += 128) ls += __expf(g_gate[i] - gm);
    red[t] = ls;
    __syncthreads();
    for (int o = 64; o; o >>= 1) { if (t < o) red[t] += red[t + o]; __syncthreads(); }
    float inv = (e > s) ? 1.f / red[0] : 0.f;
    __syncthreads();

    float acc = 0.f;
    for (int base = s; base < e; base += 128) {
        int i = base + t;
        wbuf[t] = (i < e) ? __expf(g_gate[i] - gm) * inv : 0.f;
        __syncthreads();
        int cnt = min(128, e - base);
#pragma unroll 8
        for (int j = 0; j < cnt; j++)
            acc += wbuf[j] * __half2float(g_h1h[(size_t)(base + j) * DC + t]);
        __syncthreads();
    }
    zout[g * DC + t] = acc;

    // re-zero histogram scratch for the next kernel_launch call (1024*128 >= N_NODES)
    int gid = g * 128 + t;
    if (gid < N_NODES) g_deg[gid] = 0;
    if (gid < N_GRAPH) g_gdeg[gid] = 0;
}

// ---------------- launch ----------------
extern "C" void kernel_launch(void* const* d_in, const int* in_sizes, int n_in,
                              void* d_out, int out_size) {
    const int*   x     = (const int*)d_in[0];
    const int*   ei    = (const int*)d_in[1];
    const int*   batch = (const int*)d_in[2];
    const float* emb   = (const float*)d_in[3];
    const float* lng   = (const float*)d_in[4];
    const float* lnb   = (const float*)d_in[5];
    const float* W1    = (const float*)d_in[6];
    const float* as1   = (const float*)d_in[7];
    const float* ad1   = (const float*)d_in[8];
    const float* b1    = (const float*)d_in[9];
    const float* W2    = (const float*)d_in[10];
    const float* as2   = (const float*)d_in[11];
    const float* ad2   = (const float*)d_in[12];
    const float* b2    = (const float*)d_in[13];
    const float* gw1   = (const float*)d_in[14];
    const float* gb1   = (const float*)d_in[15];
    const float* gw2   = (const float*)d_in[16];
    const float* gb2   = (const float*)d_in[17];
    float* out  = (float*)d_out;
    float* zout = out + (size_t)N_NODES * DC;

    const int node2_smem = 2 * 128 * PITCH_H * 2 + 2 * 128 * 4;               // ~70.7 KB
    const int gate_smem  = 128 * PITCH_H * 2 + 128 * PB_G * 2 + 2 * 64 * 4;   // ~53.8 KB
    cudaFuncSetAttribute(k_node2m, cudaFuncAttributeMaxDynamicSharedMemorySize, node2_smem);
    cudaFuncSetAttribute(k_gatem,  cudaFuncAttributeMaxDynamicSharedMemorySize, gate_smem);

    int nb_scan = (N_NODES + 1023) / 1024;

    // CSR build + graph segment pointers (hist/scatter: 4 edges per thread)
    int nb_h4 = (N_EDGES / 4 + 255) / 256;          // 400128 threads >= N_NODES too
    k_hist<<<nb_h4, 256>>>(ei, batch);
    k_scan_block<<<nb_scan, 1024>>>();
    k_scan_add2<<<(N_NODES + 255) / 256, 256>>>(nb_scan);
    k_scatter<<<nb_h4, 256>>>(ei);
    k_rowsortw<<<(N_NODES + WPB - 1) / WPB, NTPB>>>();

    int nb_agg  = (N_NODES + WPB - 1) / WPB;
    int nb_blk  = (N_NODES + WPB * NPW - 1) / (WPB * NPW);
    int nb_e2   = (N_EDGES / 2 + 255) / 256;
    int nb_mma  = (N_NODES + 127) / 128;

    k_node1<<<nb_blk, NTPB>>>(x, emb, lng, lnb, W1, as1, ad1);
    k_elog<<<nb_e2, 256>>>();
    k_agg<<<nb_agg, NTPB>>>(b1, nullptr, 1);
    k_node2m<<<nb_mma, NTPB, node2_smem>>>(W2, as2, ad2);
    k_elog<<<nb_e2, 256>>>();
    k_agg<<<nb_agg, NTPB>>>(b2, out, 2);
    k_gatem<<<nb_mma, NTPB, gate_smem>>>(gw1, gb1, gw2, gb2);
    k_pool<<<N_GRAPH, 128>>>(zout);
}